// round 16
// baseline (speedup 1.0000x reference)
#include <cuda_runtime.h>
#include <cuda_fp16.h>
#include <cstdint>

#define BATCH 32
#define CIN   512
#define COUT  2048
#define HEADS 8
#define NPIX  256
#define SPARSITY 7

// fp16 operand buffers
__device__ __half g_xt16 [BATCH * NPIX * CIN];    // [b][n][c]
__device__ __half g_wqkv [3 * COUT * CIN];        // Wq|Wk|Wv fp16
__device__ __half g_wo16 [COUT * COUT];
__device__ __half g_q16  [BATCH * NPIX * COUT];   // [b][n][2048]
__device__ __half g_k16  [BATCH * NPIX * COUT];   // [b][n][2048]
__device__ __half g_v16  [BATCH * COUT * NPIX];   // [b][m][n]
__device__ __half g_sa16 [BATCH * HEADS * NPIX * NPIX]; // [bh][n][m]
__device__ __half g_aot16[BATCH * NPIX * COUT];   // [b][n][2048]
__device__ float  g_attn [BATCH * HEADS * NPIX * NPIX]; // fp32

__device__ int   g_t7i[256 * SPARSITY];
__device__ float g_t7v[256 * SPARSITY];
__device__ int   g_csc_row[256 * 256];
__device__ float g_csc_val[256 * 256];
__device__ int   g_csc_cnt[256];

// ---------------------------------------------------------------------------
__device__ __forceinline__ void mma_f16(float c[4],
    unsigned a0, unsigned a1, unsigned a2, unsigned a3,
    unsigned b0, unsigned b1)
{
    asm volatile(
        "mma.sync.aligned.m16n8k16.row.col.f32.f16.f16.f32 "
        "{%0,%1,%2,%3}, {%4,%5,%6,%7}, {%8,%9}, {%0,%1,%2,%3};"
        : "+f"(c[0]), "+f"(c[1]), "+f"(c[2]), "+f"(c[3])
        : "r"(a0), "r"(a1), "r"(a2), "r"(a3), "r"(b0), "r"(b1));
}

__device__ __forceinline__ void ldsm_x4(unsigned& r0, unsigned& r1,
                                        unsigned& r2, unsigned& r3, uint32_t a)
{
    asm volatile("ldmatrix.sync.aligned.m8n8.x4.shared.b16 {%0,%1,%2,%3}, [%4];"
                 : "=r"(r0), "=r"(r1), "=r"(r2), "=r"(r3) : "r"(a));
}

__device__ __forceinline__ void cpa16(unsigned saddr, const void* gptr) {
    asm volatile("cp.async.cg.shared.global [%0], [%1], 16;\n"
                 :: "r"(saddr), "l"(gptr));
}
#define CP_COMMIT() asm volatile("cp.async.commit_group;\n")
#define CP_WAIT1()  asm volatile("cp.async.wait_group 1;\n")
#define CP_WAIT0()  asm volatile("cp.async.wait_group 0;\n")

__device__ __forceinline__ uint32_t smem_u32(const void* p) {
    uint32_t a;
    asm("{ .reg .u64 t; cvta.to.shared.u64 t, %1; cvt.u32.u64 %0, t; }"
        : "=r"(a) : "l"(p));
    return a;
}

// BM=64, BN=128, BK=64 layout constants
#define ROWB   144u        // 128B data + 16B pad per row
#define STAGE  27648u      // (64 A + 128 B rows) * 144
#define BOFFS  9216u       // B tile offset within stage (64*144)
#define NSTG   3

// ---------------------------------------------------------------------------
__global__ void cvt_all(const float4* __restrict__ Wq, const float4* __restrict__ Wk,
                        const float4* __restrict__ Wv, const float4* __restrict__ Wo,
                        __half2* __restrict__ dqkv, __half2* __restrict__ dwo,
                        int n4each, int n4o) {
    int i = blockIdx.x * blockDim.x + threadIdx.x;
    if (i < 3 * n4each) {
        int sec = i / n4each, j = i - sec * n4each;
        const float4* src = (sec == 0) ? Wq : (sec == 1) ? Wk : Wv;
        float4 v = src[j];
        dqkv[2 * i]     = __floats2half2_rn(v.x, v.y);
        dqkv[2 * i + 1] = __floats2half2_rn(v.z, v.w);
    } else {
        int j = i - 3 * n4each;
        if (j < n4o) {
            float4 v = Wo[j];
            dwo[2 * j]     = __floats2half2_rn(v.x, v.y);
            dwo[2 * j + 1] = __floats2half2_rn(v.z, v.w);
        }
    }
}

__global__ void tr_cvt16(const float* __restrict__ in, __half* __restrict__ out,
                         int C, int N) {
    __shared__ float s[32][33];
    int b = blockIdx.z;
    const float* ib = in  + (size_t)b * C * N;
    __half*      ob = out + (size_t)b * N * C;
    int c0 = blockIdx.x * 32, n0 = blockIdx.y * 32;
    int tx = threadIdx.x, ty = threadIdx.y;
    #pragma unroll
    for (int i = 0; i < 4; i++)
        s[ty + 8 * i][tx] = ib[(size_t)(c0 + ty + 8 * i) * N + n0 + tx];
    __syncthreads();
    #pragma unroll
    for (int i = 0; i < 4; i++)
        ob[(size_t)(n0 + ty + 8 * i) * C + c0 + tx] = __float2half(s[tx][ty + 8 * i]);
}

// ---------------------------------------------------------------------------
// top-7 per row, one block barrier (R15 version).
__global__ void sparsify_topk(const float* __restrict__ coeff) {
    __shared__ float cv[64];
    __shared__ int   cix[64];
    const int r = blockIdx.x, t = threadIdx.x;
    const int lane = t & 31, wid = t >> 5;
    const float* row = coeff + (size_t)r * 2048;

    float va[7]; int ia[7];
    #pragma unroll
    for (int i = 0; i < 7; i++) { va[i] = -1.0f; ia[i] = 1 << 30; }

    #pragma unroll
    for (int j = 0; j < 8; j++) {
        int idx = t + 256 * j;
        float v = fabsf(row[idx]);
        if (v > va[6] || (v == va[6] && idx < ia[6])) {
            va[6] = v; ia[6] = idx;
            #pragma unroll
            for (int s = 5; s >= 0; s--) {
                if (va[s + 1] > va[s] || (va[s + 1] == va[s] && ia[s + 1] < ia[s])) {
                    float tv = va[s]; va[s] = va[s + 1]; va[s + 1] = tv;
                    int   ti = ia[s]; ia[s] = ia[s + 1]; ia[s + 1] = ti;
                }
            }
        }
    }

    int ptr = 0;
    #pragma unroll
    for (int it = 0; it < SPARSITY; it++) {
        float cvv = (ptr < 7) ? va[ptr] : -2.0f;
        int   cii = (ptr < 7) ? ia[ptr] : (1 << 30);
        float bv = cvv; int bi = cii;
        #pragma unroll
        for (int o = 16; o > 0; o >>= 1) {
            float ov = __shfl_xor_sync(0xFFFFFFFF, bv, o);
            int   oi = __shfl_xor_sync(0xFFFFFFFF, bi, o);
            if (ov > bv || (ov == bv && oi < bi)) { bv = ov; bi = oi; }
        }
        if (lane == 0) { cv[wid * 7 + it] = bv; cix[wid * 7 + it] = bi; }
        if (cii == bi) ptr++;
    }
    __syncthreads();

    if (wid == 0) {
        float c0 = (lane < 56) ? cv[lane] : -2.0f;
        int   i0 = (lane < 56) ? cix[lane] : (1 << 30);
        float c1 = (lane + 32 < 56) ? cv[lane + 32] : -2.0f;
        int   i1 = (lane + 32 < 56) ? cix[lane + 32] : (1 << 30);
        #pragma unroll
        for (int it = 0; it < SPARSITY; it++) {
            float lv; int li;
            if (c0 > c1 || (c0 == c1 && i0 < i1)) { lv = c0; li = i0; }
            else                                  { lv = c1; li = i1; }
            float bv = lv; int bi = li;
            #pragma unroll
            for (int o = 16; o > 0; o >>= 1) {
                float ov = __shfl_xor_sync(0xFFFFFFFF, bv, o);
                int   oi = __shfl_xor_sync(0xFFFFFFFF, bi, o);
                if (ov > bv || (ov == bv && oi < bi)) { bv = ov; bi = oi; }
            }
            if (lane == 0) {
                g_t7i[r * SPARSITY + it] = bi;
                g_t7v[r * SPARSITY + it] = row[bi];
            }
            if (i0 == bi) { c0 = -2.0f; i0 = 1 << 30; }
            if (i1 == bi) { c1 = -2.0f; i1 = 1 << 30; }
        }
    }
}

// ---------------------------------------------------------------------------
// parallel CSC build (R15 version).
__global__ void build_csc() {
    __shared__ int wcnt[8];
    const int p = blockIdx.x, r = threadIdx.x;
    const int lane = r & 31, wid = r >> 5;

    int match = 0; float val = 0.0f;
    #pragma unroll
    for (int j = 0; j < SPARSITY; j++) {
        if (g_t7i[r * SPARSITY + j] == p) { match = 1; val = g_t7v[r * SPARSITY + j]; }
    }
    unsigned m = __ballot_sync(0xFFFFFFFF, match);
    int wpre = __popc(m & ((1u << lane) - 1u));
    if (lane == 0) wcnt[wid] = __popc(m);
    __syncthreads();
    int base = 0;
    #pragma unroll
    for (int w = 0; w < 8; w++) if (w < wid) base += wcnt[w];
    if (match) {
        int off = base + wpre;
        g_csc_row[p * 256 + off] = r;
        g_csc_val[p * 256 + off] = val;
    }
    if (r == 0) {
        int tot = 0;
        #pragma unroll
        for (int w = 0; w < 8; w++) tot += wcnt[w];
        g_csc_cnt[p] = tot;
    }
}

// ---------------------------------------------------------------------------
// QKV fused conv, BM=64: grid (2, 96, 32). y>>5 selects q|k|v; m0=(y&31)*64.
__global__ __launch_bounds__(256) void hgemm_qkv(
    const float* __restrict__ bq, const float* __restrict__ bk,
    const float* __restrict__ bv)
{
    extern __shared__ char smem[];
    const uint32_t sb = smem_u32(smem);

    const int z   = blockIdx.z;
    const int sec = blockIdx.y >> 5;
    const int m0  = (blockIdx.y & 31) * 64;
    const int n0  = blockIdx.x * 128;

    const __half* Ap = g_wqkv + (size_t)sec * COUT * CIN;
    const __half* Bp = g_xt16 + (size_t)z * NPIX * CIN;
    const float* bias = (sec == 0) ? bq : (sec == 1) ? bk : bv;

    const int t = threadIdx.x, lane = t & 31, wid = t >> 5;
    const int g = lane >> 2, tig = lane & 3;
    const int wm = (wid >> 2) * 32, wn = (wid & 3) * 32;

    const uint32_t aoff = (uint32_t)(wm + (lane & 15)) * ROWB + (uint32_t)(lane >> 4) * 16u;
    const int bq_ = lane >> 3;
    const uint32_t boff = (uint32_t)(wn + ((bq_ >> 1) << 3) + (lane & 7)) * ROWB
                        + (uint32_t)(bq_ & 1) * 16u;

    const int NT = CIN >> 6;   // 8

    #pragma unroll
    for (int s = 0; s < 2; s++) {
        uint32_t sA = sb + (unsigned)s * STAGE;
        uint32_t sB = sA + BOFFS;
        #pragma unroll
        for (int i = 0; i < 2; i++) {            // A: 512 chunks
            int c = t + 256 * i;
            int row = c >> 3, col16 = c & 7;
            cpa16(sA + (unsigned)row * ROWB + col16 * 16,
                  Ap + (size_t)(m0 + row) * CIN + s * 64 + col16 * 8);
        }
        #pragma unroll
        for (int i = 0; i < 4; i++) {            // B: 1024 chunks
            int c = t + 256 * i;
            int row = c >> 3, col16 = c & 7;
            cpa16(sB + (unsigned)row * ROWB + col16 * 16,
                  Bp + (size_t)(n0 + row) * CIN + s * 64 + col16 * 8);
        }
        CP_COMMIT();
    }

    float acc[2][4][4];
    #pragma unroll
    for (int i = 0; i < 2; i++)
        #pragma unroll
        for (int j = 0; j < 4; j++)
            #pragma unroll
            for (int q = 0; q < 4; q++) acc[i][j][q] = 0.0f;

    for (int it = 0; it < NT; it++) {
        int s = it % NSTG;
        if (it + 1 < NT) { CP_WAIT1(); } else { CP_WAIT0(); }
        __syncthreads();

        if (it + 2 < NT) {
            int sn = (it + 2) % NSTG, k0n = (it + 2) << 6;
            uint32_t sA = sb + (unsigned)sn * STAGE;
            uint32_t sB = sA + BOFFS;
            #pragma unroll
            for (int i = 0; i < 2; i++) {
                int c = t + 256 * i;
                int row = c >> 3, col16 = c & 7;
                cpa16(sA + (unsigned)row * ROWB + col16 * 16,
                      Ap + (size_t)(m0 + row) * CIN + k0n + col16 * 8);
            }
            #pragma unroll
            for (int i = 0; i < 4; i++) {
                int c = t + 256 * i;
                int row = c >> 3, col16 = c & 7;
                cpa16(sB + (unsigned)row * ROWB + col16 * 16,
                      Bp + (size_t)(n0 + row) * CIN + k0n + col16 * 8);
            }
            CP_COMMIT();
        }

        uint32_t sA = sb + (unsigned)s * STAGE + aoff;
        uint32_t sB = sb + (unsigned)s * STAGE + BOFFS + boff;
        #pragma unroll
        for (int kb = 0; kb < 4; kb++) {
            unsigned a[2][4], b[2][4];
            #pragma unroll
            for (int mf = 0; mf < 2; mf++)
                ldsm_x4(a[mf][0], a[mf][1], a[mf][2], a[mf][3],
                        sA + (unsigned)mf * (16u * ROWB) + (unsigned)kb * 32u);
            #pragma unroll
            for (int np = 0; np < 2; np++)
                ldsm_x4(b[np][0], b[np][1], b[np][2], b[np][3],
                        sB + (unsigned)np * (16u * ROWB) + (unsigned)kb * 32u);
            #pragma unroll
            for (int mf = 0; mf < 2; mf++)
                #pragma unroll
                for (int nf = 0; nf < 4; nf++)
                    mma_f16(acc[mf][nf], a[mf][0], a[mf][1], a[mf][2], a[mf][3],
                            b[nf >> 1][(nf & 1) * 2], b[nf >> 1][(nf & 1) * 2 + 1]);
        }
    }
    __syncthreads();

    if (sec < 2) {
        // q/k: transpose-stage [n=128][m=72 halves] then coalesced u16x8
        __half* st = (__half*)smem;
        #pragma unroll
        for (int mf = 0; mf < 2; mf++) {
            int r = wm + mf * 16 + g;
            float bv0 = bias[m0 + r], bv1 = bias[m0 + r + 8];
            #pragma unroll
            for (int nf = 0; nf < 4; nf++) {
                int cc = wn + nf * 8 + 2 * tig;
                st[(size_t)cc * 72 + r]           = __float2half(acc[mf][nf][0] + bv0);
                st[(size_t)(cc + 1) * 72 + r]     = __float2half(acc[mf][nf][1] + bv0);
                st[(size_t)cc * 72 + r + 8]       = __float2half(acc[mf][nf][2] + bv1);
                st[(size_t)(cc + 1) * 72 + r + 8] = __float2half(acc[mf][nf][3] + bv1);
            }
        }
        __syncthreads();
        __half* Ch = ((sec == 0) ? g_q16 : g_k16) + (size_t)z * 524288;
        #pragma unroll
        for (int i = 0; i < 4; i++) {
            int c = t + 256 * i;
            int n = c >> 3, col16 = c & 7;
            uint4 val = *(const uint4*)(st + (size_t)n * 72 + col16 * 8);
            *(uint4*)(Ch + (size_t)(n0 + n) * 2048 + m0 + col16 * 8) = val;
        }
        return;
    }

    __half2* Ch = (__half2*)(g_v16 + (size_t)z * 524288);
    #pragma unroll
    for (int mf = 0; mf < 2; mf++) {
        int r = wm + mf * 16 + g;
        int m = m0 + r;
        float bv0 = bias[m], bv1 = bias[m + 8];
        #pragma unroll
        for (int nf = 0; nf < 4; nf++) {
            int cc = wn + nf * 8 + 2 * tig;
            int n = n0 + cc;
            Ch[((size_t)m * 256 + n) >> 1]       = __floats2half2_rn(acc[mf][nf][0] + bv0, acc[mf][nf][1] + bv0);
            Ch[((size_t)(m + 8) * 256 + n) >> 1] = __floats2half2_rn(acc[mf][nf][2] + bv1, acc[mf][nf][3] + bv1);
        }
    }
}

// ---------------------------------------------------------------------------
// generic hgemm, BM=64: modes 2 conv->out, 3 attn, 4 av->aot
__global__ __launch_bounds__(256) void hgemm(
    const __half* __restrict__ A, const __half* __restrict__ B, void* __restrict__ C,
    int K, int lda, int ldb, int mode,
    const float* __restrict__ bias, const float* __restrict__ scale)
{
    extern __shared__ char smem[];
    const uint32_t sb = smem_u32(smem);

    const int z  = blockIdx.z;
    const int m0 = blockIdx.y * 64;
    const int n0 = blockIdx.x * 128;

    const __half *Ap, *Bp;
    if (mode == 3) {
        int b = z >> 3, h = z & 7;
        Ap = A + (size_t)b * 524288 + h * 256;
        Bp = B + (size_t)b * 524288 + h * 256;
    } else if (mode == 4) {
        int b = z >> 3, h = z & 7;
        Ap = A + (size_t)b * 524288 + h * 65536;
        Bp = B + (size_t)z * 65536;
    } else {
        Ap = A;
        Bp = B + (size_t)z * NPIX * K;
    }

    const int t = threadIdx.x, lane = t & 31, wid = t >> 5;
    const int g = lane >> 2, tig = lane & 3;
    const int wm = (wid >> 2) * 32, wn = (wid & 3) * 32;

    const uint32_t aoff = (uint32_t)(wm + (lane & 15)) * ROWB + (uint32_t)(lane >> 4) * 16u;
    const int bq = lane >> 3;
    const uint32_t boff = (uint32_t)(wn + ((bq >> 1) << 3) + (lane & 7)) * ROWB
                        + (uint32_t)(bq & 1) * 16u;

    const int NT = K >> 6;

    #pragma unroll
    for (int s = 0; s < 2; s++) {
        uint32_t sA = sb + (unsigned)s * STAGE;
        uint32_t sB = sA + BOFFS;
        #pragma unroll
        for (int i = 0; i < 2; i++) {
            int c = t + 256 * i;
            int row = c >> 3, col16 = c & 7;
            cpa16(sA + (unsigned)row * ROWB + col16 * 16,
                  Ap + (size_t)(m0 + row) * lda + s * 64 + col16 * 8);
        }
        #pragma unroll
        for (int i = 0; i < 4; i++) {
            int c = t + 256 * i;
            int row = c >> 3, col16 = c & 7;
            cpa16(sB + (unsigned)row * ROWB + col16 * 16,
                  Bp + (size_t)(n0 + row) * ldb + s * 64 + col16 * 8);
        }
        CP_COMMIT();
    }

    float acc[2][4][4];
    #pragma unroll
    for (int i = 0; i < 2; i++)
        #pragma unroll
        for (int j = 0; j < 4; j++)
            #pragma unroll
            for (int q = 0; q < 4; q++) acc[i][j][q] = 0.0f;

    for (int it = 0; it < NT; it++) {
        int s = it % NSTG;
        if (it + 1 < NT) { CP_WAIT1(); } else { CP_WAIT0(); }
        __syncthreads();

        if (it + 2 < NT) {
            int sn = (it + 2) % NSTG, k0n = (it + 2) << 6;
            uint32_t sA = sb + (unsigned)sn * STAGE;
            uint32_t sB = sA + BOFFS;
            #pragma unroll
            for (int i = 0; i < 2; i++) {
                int c = t + 256 * i;
                int row = c >> 3, col16 = c & 7;
                cpa16(sA + (unsigned)row * ROWB + col16 * 16,
                      Ap + (size_t)(m0 + row) * lda + k0n + col16 * 8);
            }
            #pragma unroll
            for (int i = 0; i < 4; i++) {
                int c = t + 256 * i;
                int row = c >> 3, col16 = c & 7;
                cpa16(sB + (unsigned)row * ROWB + col16 * 16,
                      Bp + (size_t)(n0 + row) * ldb + k0n + col16 * 8);
            }
            CP_COMMIT();
        }

        uint32_t sA = sb + (unsigned)s * STAGE + aoff;
        uint32_t sB = sb + (unsigned)s * STAGE + BOFFS + boff;
        #pragma unroll
        for (int kb = 0; kb < 4; kb++) {
            unsigned a[2][4], b[2][4];
            #pragma unroll
            for (int mf = 0; mf < 2; mf++)
                ldsm_x4(a[mf][0], a[mf][1], a[mf][2], a[mf][3],
                        sA + (unsigned)mf * (16u * ROWB) + (unsigned)kb * 32u);
            #pragma unroll
            for (int np = 0; np < 2; np++)
                ldsm_x4(b[np][0], b[np][1], b[np][2], b[np][3],
                        sB + (unsigned)np * (16u * ROWB) + (unsigned)kb * 32u);
            #pragma unroll
            for (int mf = 0; mf < 2; mf++)
                #pragma unroll
                for (int nf = 0; nf < 4; nf++)
                    mma_f16(acc[mf][nf], a[mf][0], a[mf][1], a[mf][2], a[mf][3],
                            b[nf >> 1][(nf & 1) * 2], b[nf >> 1][(nf & 1) * 2 + 1]);
        }
    }
    __syncthreads();

    const float inv = (mode == 3) ? (1.0f / __ldg(scale)) : 1.0f;

    if (mode == 4) {
        __half* st = (__half*)smem;
        #pragma unroll
        for (int mf = 0; mf < 2; mf++) {
            int r = wm + mf * 16 + g;
            #pragma unroll
            for (int nf = 0; nf < 4; nf++) {
                int cc = wn + nf * 8 + 2 * tig;
                st[(size_t)cc * 72 + r]           = __float2half(acc[mf][nf][0]);
                st[(size_t)(cc + 1) * 72 + r]     = __float2half(acc[mf][nf][1]);
                st[(size_t)cc * 72 + r + 8]       = __float2half(acc[mf][nf][2]);
                st[(size_t)(cc + 1) * 72 + r + 8] = __float2half(acc[mf][nf][3]);
            }
        }
        __syncthreads();
        int b = z >> 3, h = z & 7;
        __half* Ch = (__half*)C + (size_t)b * 524288 + h * 256;
        #pragma unroll
        for (int i = 0; i < 4; i++) {
            int c = t + 256 * i;
            int n = c >> 3, col16 = c & 7;
            uint4 val = *(const uint4*)(st + (size_t)n * 72 + col16 * 8);
            *(uint4*)(Ch + (size_t)(n0 + n) * 2048 + m0 + col16 * 8) = val;
        }
        return;
    }

    #pragma unroll
    for (int mf = 0; mf < 2; mf++) {
        int r = wm + mf * 16 + g;
        int m = m0 + r;
        float bv0 = 0.0f, bv1 = 0.0f;
        if (mode == 2) { bv0 = bias[m]; bv1 = bias[m + 8]; }
        #pragma unroll
        for (int nf = 0; nf < 4; nf++) {
            int cc = wn + nf * 8 + 2 * tig;
            int n = n0 + cc;
            float v00 = acc[mf][nf][0] + bv0, v01 = acc[mf][nf][1] + bv0;
            float v10 = acc[mf][nf][2] + bv1, v11 = acc[mf][nf][3] + bv1;
            if (mode == 2) {
                float* Cf = (float*)C + (size_t)z * 524288;
                *(float2*)(Cf + (size_t)m * 256 + n)       = make_float2(v00, v01);
                *(float2*)(Cf + (size_t)(m + 8) * 256 + n) = make_float2(v10, v11);
            } else {
                float* Cf = (float*)C + (size_t)z * 65536;
                *(float2*)(Cf + (size_t)m * 256 + n)       = make_float2(v00 * inv, v01 * inv);
                *(float2*)(Cf + (size_t)(m + 8) * 256 + n) = make_float2(v10 * inv, v11 * inv);
            }
        }
    }
}

// ---------------------------------------------------------------------------
__global__ __launch_bounds__(256) void mix_softmax()
{
    __shared__ float arow[8][256];
    const int t = threadIdx.x, lane = t & 31, wid = t >> 5;
    const size_t row = (size_t)blockIdx.x * 8 + wid;

    const float* src = g_attn + row * 256;
    #pragma unroll
    for (int i = 0; i < 8; i++) arow[wid][lane + 32 * i] = src[lane + 32 * i];
    __syncwarp();

    float sp[8];
    #pragma unroll
    for (int j = 0; j < 8; j++) {
        int p = lane + 32 * j;
        int c = g_csc_cnt[p];
        const int*   ri = g_csc_row + p * 256;
        const float* rv = g_csc_val + p * 256;
        float s = 0.0f;
        for (int jj = 0; jj < c; jj++) s += arow[wid][ri[jj]] * rv[jj];
        sp[j] = s;
    }

    float mx = sp[0];
    #pragma unroll
    for (int j = 1; j < 8; j++) mx = fmaxf(mx, sp[j]);
    #pragma unroll
    for (int o = 16; o > 0; o >>= 1) mx = fmaxf(mx, __shfl_xor_sync(0xFFFFFFFF, mx, o));

    float e[8];
    float sum = 0.0f;
    #pragma unroll
    for (int j = 0; j < 8; j++) { e[j] = __expf(sp[j] - mx); sum += e[j]; }
    #pragma unroll
    for (int o = 16; o > 0; o >>= 1) sum += __shfl_xor_sync(0xFFFFFFFF, sum, o);
    float inv = 1.0f / sum;

    __half* dst = g_sa16 + row * 256;
    #pragma unroll
    for (int j = 0; j < 8; j++) dst[lane + 32 * j] = __float2half(e[j] * inv);
}

// ---------------------------------------------------------------------------
extern "C" void kernel_launch(void* const* d_in, const int* in_sizes, int n_in,
                              void* d_out, int out_size)
{
    const float* x     = (const float*)d_in[0];
    const float* Wq    = (const float*)d_in[1];
    const float* bq    = (const float*)d_in[2];
    const float* Wk    = (const float*)d_in[3];
    const float* bk    = (const float*)d_in[4];
    const float* Wv    = (const float*)d_in[5];
    const float* bv    = (const float*)d_in[6];
    const float* Wo    = (const float*)d_in[7];
    const float* bo    = (const float*)d_in[8];
    const float* coeff = (const float*)d_in[9];
    const float* scale = (const float*)d_in[10];
    float* out = (float*)d_out;

    __half *pxt, *pwqkv, *pwo, *pq, *pk, *pv, *psa, *paot;
    float *pattn;
    cudaGetSymbolAddress((void**)&pxt,   g_xt16);
    cudaGetSymbolAddress((void**)&pwqkv, g_wqkv);
    cudaGetSymbolAddress((void**)&pwo,   g_wo16);
    cudaGetSymbolAddress((void**)&pq,    g_q16);
    cudaGetSymbolAddress((void**)&pk,    g_k16);
    cudaGetSymbolAddress((void**)&pv,    g_v16);
    cudaGetSymbolAddress((void**)&psa,   g_sa16);
    cudaGetSymbolAddress((void**)&paot,  g_aot16);
    cudaGetSymbolAddress((void**)&pattn, g_attn);

    const int SM = NSTG * STAGE;   // 82944
    cudaFuncSetAttribute(hgemm,     cudaFuncAttributeMaxDynamicSharedMemorySize, SM);
    cudaFuncSetAttribute(hgemm_qkv, cudaFuncAttributeMaxDynamicSharedMemorySize, SM);

    {
        int nw = COUT * CIN / 4;
        int no = COUT * COUT / 4;
        int tot = 3 * nw + no;
        cvt_all<<<(tot + 255) / 256, 256>>>((const float4*)Wq, (const float4*)Wk,
                                            (const float4*)Wv, (const float4*)Wo,
                                            (__half2*)pwqkv, (__half2*)pwo, nw, no);
    }
    tr_cvt16<<<dim3(CIN / 32, NPIX / 32, BATCH), dim3(32, 8)>>>(x, pxt, CIN, NPIX);

    sparsify_topk<<<256, 256>>>(coeff);
    build_csc<<<256, 256>>>();

    hgemm_qkv<<<dim3(2, 96, BATCH), 256, SM>>>(bq, bk, bv);

    hgemm<<<dim3(2, 4, BATCH * HEADS), 256, SM>>>(pq, pk, pattn, 256, 2048, 2048, 3, bq, scale);
    mix_softmax<<<BATCH * HEADS * NPIX / 8, 256>>>();
    hgemm<<<dim3(2, 4, BATCH * HEADS), 256, SM>>>(pv, psa, paot, 256, 256, 256, 4, bq, scale);

    hgemm<<<dim3(2, 32, BATCH), 256, SM>>>(pwo, paot, out, COUT, COUT, COUT, 2, bo, scale);
}

// round 17
// speedup vs baseline: 1.1598x; 1.1598x over previous
#include <cuda_runtime.h>
#include <cuda_fp16.h>
#include <cstdint>

#define BATCH 32
#define CIN   512
#define COUT  2048
#define HEADS 8
#define NPIX  256
#define SPARSITY 7

// fp16 operand buffers
__device__ __half g_xt16 [BATCH * NPIX * CIN];    // [b][n][c]
__device__ __half g_wqkv [3 * COUT * CIN];        // Wq|Wk|Wv fp16
__device__ __half g_wo16 [COUT * COUT];
__device__ __half g_q16  [BATCH * NPIX * COUT];   // [b][n][2048]
__device__ __half g_k16  [BATCH * NPIX * COUT];   // [b][n][2048]
__device__ __half g_v16  [BATCH * COUT * NPIX];   // [b][m][n]
__device__ __half g_sa16 [BATCH * HEADS * NPIX * NPIX]; // [bh][n][m]
__device__ __half g_aot16[BATCH * NPIX * COUT];   // [b][n][2048]
__device__ float  g_attn [BATCH * HEADS * NPIX * NPIX]; // fp32

__device__ int   g_t7i[256 * SPARSITY];
__device__ float g_t7v[256 * SPARSITY];
__device__ int   g_csc_row[256 * 256];
__device__ float g_csc_val[256 * 256];
__device__ int   g_csc_cnt[256];

// ---------------------------------------------------------------------------
__device__ __forceinline__ void mma_f16(float c[4],
    unsigned a0, unsigned a1, unsigned a2, unsigned a3,
    unsigned b0, unsigned b1)
{
    asm volatile(
        "mma.sync.aligned.m16n8k16.row.col.f32.f16.f16.f32 "
        "{%0,%1,%2,%3}, {%4,%5,%6,%7}, {%8,%9}, {%0,%1,%2,%3};"
        : "+f"(c[0]), "+f"(c[1]), "+f"(c[2]), "+f"(c[3])
        : "r"(a0), "r"(a1), "r"(a2), "r"(a3), "r"(b0), "r"(b1));
}

__device__ __forceinline__ void ldsm_x4(unsigned& r0, unsigned& r1,
                                        unsigned& r2, unsigned& r3, uint32_t a)
{
    asm volatile("ldmatrix.sync.aligned.m8n8.x4.shared.b16 {%0,%1,%2,%3}, [%4];"
                 : "=r"(r0), "=r"(r1), "=r"(r2), "=r"(r3) : "r"(a));
}

__device__ __forceinline__ void cpa16(unsigned saddr, const void* gptr) {
    asm volatile("cp.async.cg.shared.global [%0], [%1], 16;\n"
                 :: "r"(saddr), "l"(gptr));
}
#define CP_COMMIT() asm volatile("cp.async.commit_group;\n")
#define CP_WAIT1()  asm volatile("cp.async.wait_group 1;\n")
#define CP_WAIT0()  asm volatile("cp.async.wait_group 0;\n")

__device__ __forceinline__ uint32_t smem_u32(const void* p) {
    uint32_t a;
    asm("{ .reg .u64 t; cvta.to.shared.u64 t, %1; cvt.u32.u64 %0, t; }"
        : "=r"(a) : "l"(p));
    return a;
}

// BK=64 layout constants
#define ROWB   144u
#define STAGE  36864u
#define BOFFS  18432u
#define NSTG   3

// ---------------------------------------------------------------------------
__global__ void cvt_all(const float4* __restrict__ Wq, const float4* __restrict__ Wk,
                        const float4* __restrict__ Wv, const float4* __restrict__ Wo,
                        __half2* __restrict__ dqkv, __half2* __restrict__ dwo,
                        int n4each, int n4o) {
    int i = blockIdx.x * blockDim.x + threadIdx.x;
    if (i < 3 * n4each) {
        int sec = i / n4each, j = i - sec * n4each;
        const float4* src = (sec == 0) ? Wq : (sec == 1) ? Wk : Wv;
        float4 v = src[j];
        dqkv[2 * i]     = __floats2half2_rn(v.x, v.y);
        dqkv[2 * i + 1] = __floats2half2_rn(v.z, v.w);
    } else {
        int j = i - 3 * n4each;
        if (j < n4o) {
            float4 v = Wo[j];
            dwo[2 * j]     = __floats2half2_rn(v.x, v.y);
            dwo[2 * j + 1] = __floats2half2_rn(v.z, v.w);
        }
    }
}

__global__ void tr_cvt16(const float* __restrict__ in, __half* __restrict__ out,
                         int C, int N) {
    __shared__ float s[32][33];
    int b = blockIdx.z;
    const float* ib = in  + (size_t)b * C * N;
    __half*      ob = out + (size_t)b * N * C;
    int c0 = blockIdx.x * 32, n0 = blockIdx.y * 32;
    int tx = threadIdx.x, ty = threadIdx.y;
    #pragma unroll
    for (int i = 0; i < 4; i++)
        s[ty + 8 * i][tx] = ib[(size_t)(c0 + ty + 8 * i) * N + n0 + tx];
    __syncthreads();
    #pragma unroll
    for (int i = 0; i < 4; i++)
        ob[(size_t)(n0 + ty + 8 * i) * C + c0 + tx] = __float2half(s[tx][ty + 8 * i]);
}

// ---------------------------------------------------------------------------
// top-7 per row, one block barrier.
__global__ void sparsify_topk(const float* __restrict__ coeff) {
    __shared__ float cv[64];
    __shared__ int   cix[64];
    const int r = blockIdx.x, t = threadIdx.x;
    const int lane = t & 31, wid = t >> 5;
    const float* row = coeff + (size_t)r * 2048;

    float va[7]; int ia[7];
    #pragma unroll
    for (int i = 0; i < 7; i++) { va[i] = -1.0f; ia[i] = 1 << 30; }

    #pragma unroll
    for (int j = 0; j < 8; j++) {
        int idx = t + 256 * j;
        float v = fabsf(row[idx]);
        if (v > va[6] || (v == va[6] && idx < ia[6])) {
            va[6] = v; ia[6] = idx;
            #pragma unroll
            for (int s = 5; s >= 0; s--) {
                if (va[s + 1] > va[s] || (va[s + 1] == va[s] && ia[s + 1] < ia[s])) {
                    float tv = va[s]; va[s] = va[s + 1]; va[s + 1] = tv;
                    int   ti = ia[s]; ia[s] = ia[s + 1]; ia[s + 1] = ti;
                }
            }
        }
    }

    int ptr = 0;
    #pragma unroll
    for (int it = 0; it < SPARSITY; it++) {
        float cvv = (ptr < 7) ? va[ptr] : -2.0f;
        int   cii = (ptr < 7) ? ia[ptr] : (1 << 30);
        float bv = cvv; int bi = cii;
        #pragma unroll
        for (int o = 16; o > 0; o >>= 1) {
            float ov = __shfl_xor_sync(0xFFFFFFFF, bv, o);
            int   oi = __shfl_xor_sync(0xFFFFFFFF, bi, o);
            if (ov > bv || (ov == bv && oi < bi)) { bv = ov; bi = oi; }
        }
        if (lane == 0) { cv[wid * 7 + it] = bv; cix[wid * 7 + it] = bi; }
        if (cii == bi) ptr++;
    }
    __syncthreads();

    if (wid == 0) {
        float c0 = (lane < 56) ? cv[lane] : -2.0f;
        int   i0 = (lane < 56) ? cix[lane] : (1 << 30);
        float c1 = (lane + 32 < 56) ? cv[lane + 32] : -2.0f;
        int   i1 = (lane + 32 < 56) ? cix[lane + 32] : (1 << 30);
        #pragma unroll
        for (int it = 0; it < SPARSITY; it++) {
            float lv; int li;
            if (c0 > c1 || (c0 == c1 && i0 < i1)) { lv = c0; li = i0; }
            else                                  { lv = c1; li = i1; }
            float bv = lv; int bi = li;
            #pragma unroll
            for (int o = 16; o > 0; o >>= 1) {
                float ov = __shfl_xor_sync(0xFFFFFFFF, bv, o);
                int   oi = __shfl_xor_sync(0xFFFFFFFF, bi, o);
                if (ov > bv || (ov == bv && oi < bi)) { bv = ov; bi = oi; }
            }
            if (lane == 0) {
                g_t7i[r * SPARSITY + it] = bi;
                g_t7v[r * SPARSITY + it] = row[bi];
            }
            if (i0 == bi) { c0 = -2.0f; i0 = 1 << 30; }
            if (i1 == bi) { c1 = -2.0f; i1 = 1 << 30; }
        }
    }
}

// ---------------------------------------------------------------------------
// parallel CSC build: block per column p, thread per row r.
__global__ void build_csc() {
    __shared__ int wcnt[8];
    const int p = blockIdx.x, r = threadIdx.x;
    const int lane = r & 31, wid = r >> 5;

    int match = 0; float val = 0.0f;
    #pragma unroll
    for (int j = 0; j < SPARSITY; j++) {
        if (g_t7i[r * SPARSITY + j] == p) { match = 1; val = g_t7v[r * SPARSITY + j]; }
    }
    unsigned m = __ballot_sync(0xFFFFFFFF, match);
    int wpre = __popc(m & ((1u << lane) - 1u));
    if (lane == 0) wcnt[wid] = __popc(m);
    __syncthreads();
    int base = 0;
    #pragma unroll
    for (int w = 0; w < 8; w++) if (w < wid) base += wcnt[w];
    if (match) {
        int off = base + wpre;
        g_csc_row[p * 256 + off] = r;
        g_csc_val[p * 256 + off] = val;
    }
    if (r == 0) {
        int tot = 0;
        #pragma unroll
        for (int w = 0; w < 8; w++) tot += wcnt[w];
        g_csc_cnt[p] = tot;
    }
}

// ---------------------------------------------------------------------------
// QKV fused conv: grid (2, 48, 32). y/16 selects q|k|v. BM=BN=128, BK=64.
__global__ __launch_bounds__(256) void hgemm_qkv(
    const float* __restrict__ bq, const float* __restrict__ bk,
    const float* __restrict__ bv)
{
    extern __shared__ char smem[];
    const uint32_t sb = smem_u32(smem);

    const int z   = blockIdx.z;
    const int sec = blockIdx.y >> 4;
    const int m0  = (blockIdx.y & 15) * 128;
    const int n0  = blockIdx.x * 128;

    const __half* Ap = g_wqkv + (size_t)sec * COUT * CIN;
    const __half* Bp = g_xt16 + (size_t)z * NPIX * CIN;
    const float* bias = (sec == 0) ? bq : (sec == 1) ? bk : bv;

    const int t = threadIdx.x, lane = t & 31, wid = t >> 5;
    const int g = lane >> 2, tig = lane & 3;
    const int wm = (wid >> 2) * 64, wn = (wid & 3) * 32;

    const uint32_t aoff = (uint32_t)(wm + (lane & 15)) * ROWB + (uint32_t)(lane >> 4) * 16u;
    const int bq_ = lane >> 3;
    const uint32_t boff = (uint32_t)(wn + ((bq_ >> 1) << 3) + (lane & 7)) * ROWB
                        + (uint32_t)(bq_ & 1) * 16u;

    const int NT = CIN >> 6;

    #pragma unroll
    for (int s = 0; s < 2; s++) {
        uint32_t sA = sb + (unsigned)s * STAGE;
        uint32_t sB = sA + BOFFS;
        #pragma unroll
        for (int i = 0; i < 4; i++) {
            int c = t + 256 * i;
            int row = c >> 3, col16 = c & 7;
            cpa16(sA + (unsigned)row * ROWB + col16 * 16,
                  Ap + (size_t)(m0 + row) * CIN + s * 64 + col16 * 8);
            cpa16(sB + (unsigned)row * ROWB + col16 * 16,
                  Bp + (size_t)(n0 + row) * CIN + s * 64 + col16 * 8);
        }
        CP_COMMIT();
    }

    float acc[4][4][4];
    #pragma unroll
    for (int i = 0; i < 4; i++)
        #pragma unroll
        for (int j = 0; j < 4; j++)
            #pragma unroll
            for (int q = 0; q < 4; q++) acc[i][j][q] = 0.0f;

    for (int it = 0; it < NT; it++) {
        int s = it % NSTG;
        if (it + 1 < NT) { CP_WAIT1(); } else { CP_WAIT0(); }
        __syncthreads();

        if (it + 2 < NT) {
            int sn = (it + 2) % NSTG, k0n = (it + 2) << 6;
            uint32_t sA = sb + (unsigned)sn * STAGE;
            uint32_t sB = sA + BOFFS;
            #pragma unroll
            for (int i = 0; i < 4; i++) {
                int c = t + 256 * i;
                int row = c >> 3, col16 = c & 7;
                cpa16(sA + (unsigned)row * ROWB + col16 * 16,
                      Ap + (size_t)(m0 + row) * CIN + k0n + col16 * 8);
                cpa16(sB + (unsigned)row * ROWB + col16 * 16,
                      Bp + (size_t)(n0 + row) * CIN + k0n + col16 * 8);
            }
            CP_COMMIT();
        }

        uint32_t sA = sb + (unsigned)s * STAGE + aoff;
        uint32_t sB = sb + (unsigned)s * STAGE + BOFFS + boff;
        #pragma unroll
        for (int kb = 0; kb < 4; kb++) {
            unsigned a[4][4], b[2][4];
            #pragma unroll
            for (int mf = 0; mf < 4; mf++)
                ldsm_x4(a[mf][0], a[mf][1], a[mf][2], a[mf][3],
                        sA + (unsigned)mf * (16u * ROWB) + (unsigned)kb * 32u);
            #pragma unroll
            for (int np = 0; np < 2; np++)
                ldsm_x4(b[np][0], b[np][1], b[np][2], b[np][3],
                        sB + (unsigned)np * (16u * ROWB) + (unsigned)kb * 32u);
            #pragma unroll
            for (int mf = 0; mf < 4; mf++)
                #pragma unroll
                for (int nf = 0; nf < 4; nf++)
                    mma_f16(acc[mf][nf], a[mf][0], a[mf][1], a[mf][2], a[mf][3],
                            b[nf >> 1][(nf & 1) * 2], b[nf >> 1][(nf & 1) * 2 + 1]);
        }
    }
    __syncthreads();

    if (sec < 2) {
        __half* st = (__half*)smem;
        #pragma unroll
        for (int mf = 0; mf < 4; mf++) {
            int r = wm + mf * 16 + g;
            float bv0 = bias[m0 + r], bv1 = bias[m0 + r + 8];
            #pragma unroll
            for (int nf = 0; nf < 4; nf++) {
                int cc = wn + nf * 8 + 2 * tig;
                st[(size_t)cc * 136 + r]           = __float2half(acc[mf][nf][0] + bv0);
                st[(size_t)(cc + 1) * 136 + r]     = __float2half(acc[mf][nf][1] + bv0);
                st[(size_t)cc * 136 + r + 8]       = __float2half(acc[mf][nf][2] + bv1);
                st[(size_t)(cc + 1) * 136 + r + 8] = __float2half(acc[mf][nf][3] + bv1);
            }
        }
        __syncthreads();
        __half* Ch = ((sec == 0) ? g_q16 : g_k16) + (size_t)z * 524288;
        #pragma unroll
        for (int i = 0; i < 8; i++) {
            int c = t + 256 * i;
            int n = c >> 4, col16 = c & 15;
            uint4 val = *(const uint4*)(st + (size_t)n * 136 + col16 * 8);
            *(uint4*)(Ch + (size_t)(n0 + n) * 2048 + m0 + col16 * 8) = val;
        }
        return;
    }

    __half2* Ch = (__half2*)(g_v16 + (size_t)z * 524288);
    #pragma unroll
    for (int mf = 0; mf < 4; mf++) {
        int r = wm + mf * 16 + g;
        int m = m0 + r;
        float bv0 = bias[m], bv1 = bias[m + 8];
        #pragma unroll
        for (int nf = 0; nf < 4; nf++) {
            int cc = wn + nf * 8 + 2 * tig;
            int n = n0 + cc;
            Ch[((size_t)m * 256 + n) >> 1]       = __floats2half2_rn(acc[mf][nf][0] + bv0, acc[mf][nf][1] + bv0);
            Ch[((size_t)(m + 8) * 256 + n) >> 1] = __floats2half2_rn(acc[mf][nf][2] + bv1, acc[mf][nf][3] + bv1);
        }
    }
}

// ---------------------------------------------------------------------------
// generic hgemm: modes 2 conv->out, 3 attn, 4 av->aot. BM=BN=128, BK=64.
__global__ __launch_bounds__(256) void hgemm(
    const __half* __restrict__ A, const __half* __restrict__ B, void* __restrict__ C,
    int K, int lda, int ldb, int mode,
    const float* __restrict__ bias, const float* __restrict__ scale)
{
    extern __shared__ char smem[];
    const uint32_t sb = smem_u32(smem);

    const int z  = blockIdx.z;
    const int m0 = blockIdx.y * 128;
    const int n0 = blockIdx.x * 128;

    const __half *Ap, *Bp;
    if (mode == 3) {
        int b = z >> 3, h = z & 7;
        Ap = A + (size_t)b * 524288 + h * 256;
        Bp = B + (size_t)b * 524288 + h * 256;
    } else if (mode == 4) {
        int b = z >> 3, h = z & 7;
        Ap = A + (size_t)b * 524288 + h * 65536;
        Bp = B + (size_t)z * 65536;
    } else {
        Ap = A;
        Bp = B + (size_t)z * NPIX * K;
    }

    const int t = threadIdx.x, lane = t & 31, wid = t >> 5;
    const int g = lane >> 2, tig = lane & 3;
    const int wm = (wid >> 2) * 64, wn = (wid & 3) * 32;

    const uint32_t aoff = (uint32_t)(wm + (lane & 15)) * ROWB + (uint32_t)(lane >> 4) * 16u;
    const int bq = lane >> 3;
    const uint32_t boff = (uint32_t)(wn + ((bq >> 1) << 3) + (lane & 7)) * ROWB
                        + (uint32_t)(bq & 1) * 16u;

    const int NT = K >> 6;

    #pragma unroll
    for (int s = 0; s < 2; s++) {
        uint32_t sA = sb + (unsigned)s * STAGE;
        uint32_t sB = sA + BOFFS;
        #pragma unroll
        for (int i = 0; i < 4; i++) {
            int c = t + 256 * i;
            int row = c >> 3, col16 = c & 7;
            cpa16(sA + (unsigned)row * ROWB + col16 * 16,
                  Ap + (size_t)(m0 + row) * lda + s * 64 + col16 * 8);
            cpa16(sB + (unsigned)row * ROWB + col16 * 16,
                  Bp + (size_t)(n0 + row) * ldb + s * 64 + col16 * 8);
        }
        CP_COMMIT();
    }

    float acc[4][4][4];
    #pragma unroll
    for (int i = 0; i < 4; i++)
        #pragma unroll
        for (int j = 0; j < 4; j++)
            #pragma unroll
            for (int q = 0; q < 4; q++) acc[i][j][q] = 0.0f;

    for (int it = 0; it < NT; it++) {
        int s = it % NSTG;
        if (it + 1 < NT) { CP_WAIT1(); } else { CP_WAIT0(); }
        __syncthreads();

        if (it + 2 < NT) {
            int sn = (it + 2) % NSTG, k0n = (it + 2) << 6;
            uint32_t sA = sb + (unsigned)sn * STAGE;
            uint32_t sB = sA + BOFFS;
            #pragma unroll
            for (int i = 0; i < 4; i++) {
                int c = t + 256 * i;
                int row = c >> 3, col16 = c & 7;
                cpa16(sA + (unsigned)row * ROWB + col16 * 16,
                      Ap + (size_t)(m0 + row) * lda + k0n + col16 * 8);
                cpa16(sB + (unsigned)row * ROWB + col16 * 16,
                      Bp + (size_t)(n0 + row) * ldb + k0n + col16 * 8);
            }
            CP_COMMIT();
        }

        uint32_t sA = sb + (unsigned)s * STAGE + aoff;
        uint32_t sB = sb + (unsigned)s * STAGE + BOFFS + boff;
        #pragma unroll
        for (int kb = 0; kb < 4; kb++) {
            unsigned a[4][4], b[2][4];
            #pragma unroll
            for (int mf = 0; mf < 4; mf++)
                ldsm_x4(a[mf][0], a[mf][1], a[mf][2], a[mf][3],
                        sA + (unsigned)mf * (16u * ROWB) + (unsigned)kb * 32u);
            #pragma unroll
            for (int np = 0; np < 2; np++)
                ldsm_x4(b[np][0], b[np][1], b[np][2], b[np][3],
                        sB + (unsigned)np * (16u * ROWB) + (unsigned)kb * 32u);
            #pragma unroll
            for (int mf = 0; mf < 4; mf++)
                #pragma unroll
                for (int nf = 0; nf < 4; nf++)
                    mma_f16(acc[mf][nf], a[mf][0], a[mf][1], a[mf][2], a[mf][3],
                            b[nf >> 1][(nf & 1) * 2], b[nf >> 1][(nf & 1) * 2 + 1]);
        }
    }
    __syncthreads();

    const float inv = (mode == 3) ? (1.0f / __ldg(scale)) : 1.0f;

    if (mode == 4) {
        __half* st = (__half*)smem;
        #pragma unroll
        for (int mf = 0; mf < 4; mf++) {
            int r = wm + mf * 16 + g;
            #pragma unroll
            for (int nf = 0; nf < 4; nf++) {
                int cc = wn + nf * 8 + 2 * tig;
                st[(size_t)cc * 136 + r]           = __float2half(acc[mf][nf][0]);
                st[(size_t)(cc + 1) * 136 + r]     = __float2half(acc[mf][nf][1]);
                st[(size_t)cc * 136 + r + 8]       = __float2half(acc[mf][nf][2]);
                st[(size_t)(cc + 1) * 136 + r + 8] = __float2half(acc[mf][nf][3]);
            }
        }
        __syncthreads();
        int b = z >> 3, h = z & 7;
        __half* Ch = (__half*)C + (size_t)b * 524288 + h * 256;
        #pragma unroll
        for (int i = 0; i < 8; i++) {
            int c = t + 256 * i;
            int n = c >> 4, col16 = c & 15;
            uint4 val = *(const uint4*)(st + (size_t)n * 136 + col16 * 8);
            *(uint4*)(Ch + (size_t)(n0 + n) * 2048 + m0 + col16 * 8) = val;
        }
        return;
    }

    #pragma unroll
    for (int mf = 0; mf < 4; mf++) {
        int r = wm + mf * 16 + g;
        int m = m0 + r;
        float bv0 = 0.0f, bv1 = 0.0f;
        if (mode == 2) { bv0 = bias[m]; bv1 = bias[m + 8]; }
        #pragma unroll
        for (int nf = 0; nf < 4; nf++) {
            int cc = wn + nf * 8 + 2 * tig;
            int n = n0 + cc;
            float v00 = acc[mf][nf][0] + bv0, v01 = acc[mf][nf][1] + bv0;
            float v10 = acc[mf][nf][2] + bv1, v11 = acc[mf][nf][3] + bv1;
            if (mode == 2) {
                float* Cf = (float*)C + (size_t)z * 524288;
                *(float2*)(Cf + (size_t)m * 256 + n)       = make_float2(v00, v01);
                *(float2*)(Cf + (size_t)(m + 8) * 256 + n) = make_float2(v10, v11);
            } else {
                float* Cf = (float*)C + (size_t)z * 65536;
                *(float2*)(Cf + (size_t)m * 256 + n)       = make_float2(v00 * inv, v01 * inv);
                *(float2*)(Cf + (size_t)(m + 8) * 256 + n) = make_float2(v10 * inv, v11 * inv);
            }
        }
    }
}

// ---------------------------------------------------------------------------
__global__ __launch_bounds__(256) void mix_softmax()
{
    __shared__ float arow[8][256];
    const int t = threadIdx.x, lane = t & 31, wid = t >> 5;
    const size_t row = (size_t)blockIdx.x * 8 + wid;

    const float* src = g_attn + row * 256;
    #pragma unroll
    for (int i = 0; i < 8; i++) arow[wid][lane + 32 * i] = src[lane + 32 * i];
    __syncwarp();

    float sp[8];
    #pragma unroll
    for (int j = 0; j < 8; j++) {
        int p = lane + 32 * j;
        int c = g_csc_cnt[p];
        const int*   ri = g_csc_row + p * 256;
        const float* rv = g_csc_val + p * 256;
        float s = 0.0f;
        for (int jj = 0; jj < c; jj++) s += arow[wid][ri[jj]] * rv[jj];
        sp[j] = s;
    }

    float mx = sp[0];
    #pragma unroll
    for (int j = 1; j < 8; j++) mx = fmaxf(mx, sp[j]);
    #pragma unroll
    for (int o = 16; o > 0; o >>= 1) mx = fmaxf(mx, __shfl_xor_sync(0xFFFFFFFF, mx, o));

    float e[8];
    float sum = 0.0f;
    #pragma unroll
    for (int j = 0; j < 8; j++) { e[j] = __expf(sp[j] - mx); sum += e[j]; }
    #pragma unroll
    for (int o = 16; o > 0; o >>= 1) sum += __shfl_xor_sync(0xFFFFFFFF, sum, o);
    float inv = 1.0f / sum;

    __half* dst = g_sa16 + row * 256;
    #pragma unroll
    for (int j = 0; j < 8; j++) dst[lane + 32 * j] = __float2half(e[j] * inv);
}

// ---------------------------------------------------------------------------
extern "C" void kernel_launch(void* const* d_in, const int* in_sizes, int n_in,
                              void* d_out, int out_size)
{
    const float* x     = (const float*)d_in[0];
    const float* Wq    = (const float*)d_in[1];
    const float* bq    = (const float*)d_in[2];
    const float* Wk    = (const float*)d_in[3];
    const float* bk    = (const float*)d_in[4];
    const float* Wv    = (const float*)d_in[5];
    const float* bv    = (const float*)d_in[6];
    const float* Wo    = (const float*)d_in[7];
    const float* bo    = (const float*)d_in[8];
    const float* coeff = (const float*)d_in[9];
    const float* scale = (const float*)d_in[10];
    float* out = (float*)d_out;

    __half *pxt, *pwqkv, *pwo, *pq, *pk, *pv, *psa, *paot;
    float *pattn;
    cudaGetSymbolAddress((void**)&pxt,   g_xt16);
    cudaGetSymbolAddress((void**)&pwqkv, g_wqkv);
    cudaGetSymbolAddress((void**)&pwo,   g_wo16);
    cudaGetSymbolAddress((void**)&pq,    g_q16);
    cudaGetSymbolAddress((void**)&pk,    g_k16);
    cudaGetSymbolAddress((void**)&pv,    g_v16);
    cudaGetSymbolAddress((void**)&psa,   g_sa16);
    cudaGetSymbolAddress((void**)&paot,  g_aot16);
    cudaGetSymbolAddress((void**)&pattn, g_attn);

    const int SM = NSTG * STAGE;   // 110592
    cudaFuncSetAttribute(hgemm,     cudaFuncAttributeMaxDynamicSharedMemorySize, SM);
    cudaFuncSetAttribute(hgemm_qkv, cudaFuncAttributeMaxDynamicSharedMemorySize, SM);

    {
        int nw = COUT * CIN / 4;
        int no = COUT * COUT / 4;
        int tot = 3 * nw + no;
        cvt_all<<<(tot + 255) / 256, 256>>>((const float4*)Wq, (const float4*)Wk,
                                            (const float4*)Wv, (const float4*)Wo,
                                            (__half2*)pwqkv, (__half2*)pwo, nw, no);
    }
    tr_cvt16<<<dim3(CIN / 32, NPIX / 32, BATCH), dim3(32, 8)>>>(x, pxt, CIN, NPIX);

    sparsify_topk<<<256, 256>>>(coeff);
    build_csc<<<256, 256>>>();

    hgemm_qkv<<<dim3(2, 48, BATCH), 256, SM>>>(bq, bk, bv);

    hgemm<<<dim3(2, 2, BATCH * HEADS), 256, SM>>>(pq, pk, pattn, 256, 2048, 2048, 3, bq, scale);
    mix_softmax<<<BATCH * HEADS * NPIX / 8, 256>>>();
    hgemm<<<dim3(2, 2, BATCH * HEADS), 256, SM>>>(pv, psa, paot, 256, 256, 256, 4, bq, scale);

    hgemm<<<dim3(2, 16, BATCH), 256, SM>>>(pwo, paot, out, COUT, COUT, COUT, 2, bo, scale);
}